// round 2
// baseline (speedup 1.0000x reference)
#include <cuda_runtime.h>
#include <cstdint>

#define BATCH 64
#define SEQ   2048
#define HD    64
#define BM    128
#define BN    64
#define NKT   (SEQ / BN)          /* 32 key tiles */
#define PSTR  68                  /* P/Q plane: 8row x 4col fp32 pattern conflict-free */
#define KPSTR 136                 /* packed hi/lo K plane: %32==8 -> LDS.64 conflict-free */
#define VSTR  72                  /* V plane: 4row x 8col pattern conflict-free */

#define SP_FLOATS   (BM * PSTR)           /* 8704 */
#define KP_FLOATS   (BN * KPSTR)          /* 8704 per buffer */
#define KRAW_FLOATS (BN * HD)             /* 4096 per buffer */
#define SV_FLOATS   (BN * VSTR)           /* 4608 per buffer */
#define SMEM_FLOATS (SP_FLOATS + 2*KP_FLOATS + 2*KRAW_FLOATS + 2*SV_FLOATS)
#define SMEM_BYTES  (SMEM_FLOATS * 4)

__device__ __forceinline__ uint32_t f2tf(float x) {
    uint32_t u; asm("cvt.rna.tf32.f32 %0, %1;" : "=r"(u) : "f"(x)); return u;
}
__device__ __forceinline__ float ex2f(float x) {
    float y; asm("ex2.approx.ftz.f32 %0, %1;" : "=f"(y) : "f"(x)); return y;
}
__device__ __forceinline__ void mma_tf32(float d[4], const uint32_t a[4],
                                         uint32_t b0, uint32_t b1) {
    asm volatile(
        "mma.sync.aligned.m16n8k8.row.col.f32.tf32.tf32.f32 "
        "{%0,%1,%2,%3}, {%4,%5,%6,%7}, {%8,%9}, {%0,%1,%2,%3};\n"
        : "+f"(d[0]), "+f"(d[1]), "+f"(d[2]), "+f"(d[3])
        : "r"(a[0]), "r"(a[1]), "r"(a[2]), "r"(a[3]), "r"(b0), "r"(b1));
}
__device__ __forceinline__ void cp16(uint32_t saddr, const void* gaddr) {
    asm volatile("cp.async.cg.shared.global [%0], [%1], 16;\n"
                 :: "r"(saddr), "l"(gaddr) : "memory");
}

// K raw -> coalesced [64][64]; V -> [64][VSTR] (converted in place later)
__device__ __forceinline__ void prefetch_tile(const float* __restrict__ gK,
                                              const float* __restrict__ gV,
                                              float* rawK, float* sVbuf, int tid) {
#pragma unroll
    for (int i = 0; i < 4; i++) {
        int lin = tid + i * 256;
        int row = lin >> 4, c4 = lin & 15;
        cp16((uint32_t)__cvta_generic_to_shared(rawK + row * HD + c4 * 4),
             gK + row * HD + c4 * 4);
    }
#pragma unroll
    for (int i = 0; i < 4; i++) {
        int lin = tid + i * 256;
        int row = lin >> 4, c4 = lin & 15;
        cp16((uint32_t)__cvta_generic_to_shared(sVbuf + row * VSTR + c4 * 4),
             gV + row * HD + c4 * 4);
    }
}

__global__ void __launch_bounds__(256, 1)
attn_tf32_kernel(const float* __restrict__ Q, const float* __restrict__ K,
                 const float* __restrict__ V, float* __restrict__ O)
{
    extern __shared__ float sm[];
    float* sP    = sm;                         // [128][68] Q staging, then P (tf32 bits)
    float* sKp   = sm + SP_FLOATS;             // [2][64][136] packed {hi,lo}
    float* sKraw = sKp + 2 * KP_FLOATS;        // [2][64][64] raw fp32 K
    float* sV    = sKraw + 2 * KRAW_FLOATS;    // [2][64][72] fp32 -> tf32 in place

    const int tid  = threadIdx.x;
    const int warp = tid >> 5;
    const int lane = tid & 31;
    const int g = lane >> 2;
    const int c = lane & 3;

    const int qt = blockIdx.x;
    const int b  = blockIdx.y;

    const float* Qb = Q + ((size_t)b * SEQ + (size_t)qt * BM) * HD;
    const float* Kb = K + (size_t)b * SEQ * HD;
    const float* Vb = V + (size_t)b * SEQ * HD;
    float*       Ob = O + ((size_t)b * SEQ + (size_t)qt * BM) * HD;

    // ---- prefetch first K/V tile (buffer 0) ----
    prefetch_tile(Kb, Vb, sKraw, sV, tid);
    asm volatile("cp.async.commit_group;\n" ::: "memory");

    // ---- stage Q tile ----
#pragma unroll
    for (int i = 0; i < 8; i++) {
        int lin = tid + i * 256;
        int row = lin >> 4, c4 = lin & 15;
        float4 v = *(const float4*)(Qb + row * HD + c4 * 4);
        *(float4*)(sP + row * PSTR + c4 * 4) = v;
    }
    __syncthreads();

    // ---- Q fragments: scale*log2e folded, tf32 hi/lo in registers ----
    const float qscale = 0.125f * 1.4426950408889634f;
    uint32_t qh[8][4], ql[8][4];
#pragma unroll
    for (int ks = 0; ks < 8; ks++) {
        int r0 = warp * 16 + g;
        int cc = ks * 8 + c;
        float q0 = sP[r0 * PSTR + cc] * qscale;
        float q1 = sP[(r0 + 8) * PSTR + cc] * qscale;
        float q2 = sP[r0 * PSTR + cc + 4] * qscale;
        float q3 = sP[(r0 + 8) * PSTR + cc + 4] * qscale;
        qh[ks][0] = f2tf(q0); ql[ks][0] = f2tf(q0 - __uint_as_float(qh[ks][0]));
        qh[ks][1] = f2tf(q1); ql[ks][1] = f2tf(q1 - __uint_as_float(qh[ks][1]));
        qh[ks][2] = f2tf(q2); ql[ks][2] = f2tf(q2 - __uint_as_float(qh[ks][2]));
        qh[ks][3] = f2tf(q3); ql[ks][3] = f2tf(q3 - __uint_as_float(qh[ks][3]));
    }

    float oacc[8][4];
#pragma unroll
    for (int nt = 0; nt < 8; nt++) {
        oacc[nt][0] = 0.f; oacc[nt][1] = 0.f; oacc[nt][2] = 0.f; oacc[nt][3] = 0.f;
    }
    float mA = -1e30f, mB = -1e30f, lA = 0.f, lB = 0.f;

    for (int kb = 0; kb < NKT; kb++) {
        const int cur = kb & 1;
        if (kb + 1 < NKT) {
            prefetch_tile(Kb + (size_t)(kb + 1) * BN * HD,
                          Vb + (size_t)(kb + 1) * BN * HD,
                          sKraw + (cur ^ 1) * KRAW_FLOATS,
                          sV + (cur ^ 1) * SV_FLOATS, tid);
            asm volatile("cp.async.commit_group;\n" ::: "memory");
            asm volatile("cp.async.wait_group 1;\n" ::: "memory");
        } else {
            asm volatile("cp.async.wait_group 0;\n" ::: "memory");
        }
        __syncthreads();   // raw K/V of current buffer landed

        float* Kp   = sKp + cur * KP_FLOATS;
        float* Kraw = sKraw + cur * KRAW_FLOATS;
        float* Vt   = sV + cur * SV_FLOATS;

        // ---- cooperative tf32 conversion (once per tile, not per warp) ----
#pragma unroll
        for (int i = 0; i < 16; i++) {
            int lin = tid + i * 256;         // 4096 K elems
            int row = lin >> 6, col = lin & 63;
            float f = Kraw[row * HD + col];
            uint32_t hi = f2tf(f);
            uint32_t lo = f2tf(f - __uint_as_float(hi));
            *(float2*)(Kp + row * KPSTR + 2 * col) =
                make_float2(__uint_as_float(hi), __uint_as_float(lo));
        }
#pragma unroll
        for (int i = 0; i < 16; i++) {
            int lin = tid + i * 256;         // 4096 V elems, in place
            int row = lin >> 6, col = lin & 63;
            float f = Vt[row * VSTR + col];
            Vt[row * VSTR + col] = __uint_as_float(f2tf(f));
        }
        __syncthreads();   // converted planes visible

        // ---- S = Q K^T (3xTF32), inner loop = pure LDS.64 + MMA ----
        float sacc[8][4];
#pragma unroll
        for (int nt = 0; nt < 8; nt++) {
            sacc[nt][0] = 0.f; sacc[nt][1] = 0.f; sacc[nt][2] = 0.f; sacc[nt][3] = 0.f;
        }
#pragma unroll
        for (int ks = 0; ks < 8; ks++) {
#pragma unroll
            for (int nt = 0; nt < 8; nt++) {
                float2 k0 = *(const float2*)(Kp + (nt * 8 + g) * KPSTR + 2 * (ks * 8 + c));
                float2 k1 = *(const float2*)(Kp + (nt * 8 + g) * KPSTR + 2 * (ks * 8 + c + 4));
                uint32_t bh0 = __float_as_uint(k0.x), bl0 = __float_as_uint(k0.y);
                uint32_t bh1 = __float_as_uint(k1.x), bl1 = __float_as_uint(k1.y);
                mma_tf32(sacc[nt], qh[ks], bh0, bh1);
                mma_tf32(sacc[nt], qh[ks], bl0, bl1);
                mma_tf32(sacc[nt], ql[ks], bh0, bh1);
            }
        }

        // ---- online softmax (base 2) ----
        float mAn = mA, mBn = mB;
#pragma unroll
        for (int nt = 0; nt < 8; nt++) {
            mAn = fmaxf(mAn, fmaxf(sacc[nt][0], sacc[nt][1]));
            mBn = fmaxf(mBn, fmaxf(sacc[nt][2], sacc[nt][3]));
        }
        mAn = fmaxf(mAn, __shfl_xor_sync(0xffffffffu, mAn, 1));
        mAn = fmaxf(mAn, __shfl_xor_sync(0xffffffffu, mAn, 2));
        mBn = fmaxf(mBn, __shfl_xor_sync(0xffffffffu, mBn, 1));
        mBn = fmaxf(mBn, __shfl_xor_sync(0xffffffffu, mBn, 2));

        float aA = ex2f(mA - mAn), aB = ex2f(mB - mBn);
        float sumA = 0.f, sumB = 0.f;
#pragma unroll
        for (int nt = 0; nt < 8; nt++) {
            sacc[nt][0] = ex2f(sacc[nt][0] - mAn); sumA += sacc[nt][0];
            sacc[nt][1] = ex2f(sacc[nt][1] - mAn); sumA += sacc[nt][1];
            sacc[nt][2] = ex2f(sacc[nt][2] - mBn); sumB += sacc[nt][2];
            sacc[nt][3] = ex2f(sacc[nt][3] - mBn); sumB += sacc[nt][3];
        }
        sumA += __shfl_xor_sync(0xffffffffu, sumA, 1);
        sumA += __shfl_xor_sync(0xffffffffu, sumA, 2);
        sumB += __shfl_xor_sync(0xffffffffu, sumB, 1);
        sumB += __shfl_xor_sync(0xffffffffu, sumB, 2);
        lA = lA * aA + sumA; lB = lB * aB + sumB;
        mA = mAn; mB = mBn;
#pragma unroll
        for (int nt = 0; nt < 8; nt++) {
            oacc[nt][0] *= aA; oacc[nt][1] *= aA;
            oacc[nt][2] *= aB; oacc[nt][3] *= aB;
        }

        // ---- P -> smem as tf32 bits (convert at store; per-warp private rows) ----
#pragma unroll
        for (int nt = 0; nt < 8; nt++) {
            int r0 = warp * 16 + g;
            *(float2*)(sP + r0 * PSTR + nt * 8 + 2 * c) =
                make_float2(__uint_as_float(f2tf(sacc[nt][0])),
                            __uint_as_float(f2tf(sacc[nt][1])));
            *(float2*)(sP + (r0 + 8) * PSTR + nt * 8 + 2 * c) =
                make_float2(__uint_as_float(f2tf(sacc[nt][2])),
                            __uint_as_float(f2tf(sacc[nt][3])));
        }
        __syncwarp();

        // ---- O += P V : pure LDS + MMA ----
#pragma unroll
        for (int ks = 0; ks < 8; ks++) {
            int r0 = warp * 16 + g;
            int pc = ks * 8 + c;
            uint32_t a[4];
            a[0] = __float_as_uint(sP[r0 * PSTR + pc]);
            a[1] = __float_as_uint(sP[(r0 + 8) * PSTR + pc]);
            a[2] = __float_as_uint(sP[r0 * PSTR + pc + 4]);
            a[3] = __float_as_uint(sP[(r0 + 8) * PSTR + pc + 4]);
#pragma unroll
            for (int nt = 0; nt < 8; nt++) {
                uint32_t b0 = __float_as_uint(Vt[(ks * 8 + c) * VSTR + nt * 8 + g]);
                uint32_t b1 = __float_as_uint(Vt[(ks * 8 + c + 4) * VSTR + nt * 8 + g]);
                mma_tf32(oacc[nt], a, b0, b1);
            }
        }
        __syncthreads();   // done with cur buffers before next prefetch reuses them
    }

    // ---- epilogue ----
    float iA = 1.f / lA, iB = 1.f / lB;
#pragma unroll
    for (int nt = 0; nt < 8; nt++) {
        int r0 = warp * 16 + g;
        *(float2*)(Ob + r0 * HD + nt * 8 + 2 * c) =
            make_float2(oacc[nt][0] * iA, oacc[nt][1] * iA);
        *(float2*)(Ob + (r0 + 8) * HD + nt * 8 + 2 * c) =
            make_float2(oacc[nt][2] * iB, oacc[nt][3] * iB);
    }
}

extern "C" void kernel_launch(void* const* d_in, const int* in_sizes, int n_in,
                              void* d_out, int out_size) {
    (void)in_sizes; (void)n_in; (void)out_size;
    const float* Q = (const float*)d_in[0];
    const float* K = (const float*)d_in[1];
    const float* V = (const float*)d_in[2];
    float* O = (float*)d_out;

    cudaFuncSetAttribute(attn_tf32_kernel,
                         cudaFuncAttributeMaxDynamicSharedMemorySize, SMEM_BYTES);
    dim3 grid(SEQ / BM, BATCH);
    attn_tf32_kernel<<<grid, 256, SMEM_BYTES>>>(Q, K, V, O);
}